// round 16
// baseline (speedup 1.0000x reference)
#include <cuda_runtime.h>
#include <cuda_pipeline_primitives.h>

// Shapes (fixed by the problem config)
#define B_   8
#define C_   64
#define T_   50
#define H_   64
#define W_   64
#define HO_  32
#define WO_  32
#define HW_  (H_ * W_)     // 4096 floats per (b,c,t) plane
#define OHW_ (HO_ * WO_)   // 1024
#define N_OUT ((long long)B_ * C_ * T_ * HO_ * WO_)  // 26,214,400

// Persistent double-buffered kernel. Region = ONE window-row (2 h-rows) x
// 64 w x 50 t = 25.6KB. Each block holds TWO region buffers (51.2KB smem)
// and grid-strides over regions, prefetching region i+1 via cp.async while
// computing/writing region i — the LDGSTS pipe never drains at region
// boundaries (the one-shot variants drained it 16384 times).
#define REG_FLOATS (2 * 64 * T_)          // 6400 floats per region
#define REG_F4     (REG_FLOATS / 4)       // 1600 float4s
#define BUF_BYTES  (REG_FLOATS * 4)       // 25600
#define SMEM_BYTES (2 * BUF_BYTES)        // 51200 (double buffer)
#define NWIN 32                           // windows per region
#define NTHREADS 256
#define NREGIONS (B_ * C_ * 32)           // 16384
#define NBLOCKS  (152 * 4)                // 4 blocks/SM on GB300 (152 SMs)

__device__ __forceinline__ void prefetch_region(const float* __restrict__ x,
                                                float* __restrict__ buf,
                                                int region, int tid) {
    const int bc = region >> 5;
    const int r  = region & 31;
    const float4* gp = (const float4*)(x + (size_t)bc * (T_ * HW_) + (size_t)r * 128);
    float4* shp = (float4*)buf;
    #pragma unroll
    for (int j = 0; j < 7; ++j) {          // 1600 f4 / 256 thr = 6.25 -> 7
        const int l = j * NTHREADS + tid;
        if (l < REG_F4) {
            const int t = l >> 5;          // 32 float4 per region-plane
            const int w = l & 31;
            __pipeline_memcpy_async(&shp[l], &gp[(size_t)t * (HW_ / 4) + w],
                                    sizeof(float4));
        }
    }
}

__global__ __launch_bounds__(NTHREADS, 4)
void spike_pool_persist(const float* __restrict__ x, float* __restrict__ out,
                        long long total_out) {
    const int tid = threadIdx.x;
    extern __shared__ float sh[];          // two region buffers back-to-back
    __shared__ int sidx[NWIN];

    // Zero the out tail (loss scalar / padding) once.
    if (blockIdx.x == 0 && tid == 0) {
        for (long long i = N_OUT; i < total_out; ++i) out[i] = 0.0f;
    }

    // Prologue: prefetch this block's first region into buffer 0.
    int region = blockIdx.x;
    if (region < NREGIONS) prefetch_region(x, sh, region, tid);
    __pipeline_commit();

    int cur = 0;
    for (; region < NREGIONS; region += NBLOCKS) {
        // Prefetch the NEXT region into the idle buffer (free since the
        // previous iteration's trailing __syncthreads).
        const int nxt = region + NBLOCKS;
        if (nxt < NREGIONS)
            prefetch_region(x, sh + (1 - cur) * REG_FLOATS, nxt, tid);
        __pipeline_commit();

        __pipeline_wait_prior(1);          // current buffer resident
        __syncthreads();

        const float* buf = sh + cur * REG_FLOATS;
        const int bc = region >> 5;
        const int r  = region & 31;

        // ---- Phase 1: one thread per (window, pixel), tid < 128. FP order
        //      identical to the rel_err==0 kernels; first-max via shfl. ----
        if (tid < 4 * NWIN) {
            const int w = tid >> 2;
            const int p = tid & 3;
            const int off = 2 * w + (p >> 1) * 64 + (p & 1);

            float a = 0.f, s = 0.f;
            #pragma unroll 10
            for (int t = 0; t < T_; ++t) {
                a += buf[t * 128 + off];
                s += a;
            }

            const unsigned full = 0xFFFFFFFFu;
            const int base = (tid & 31) & ~3;
            const float s0 = __shfl_sync(full, s, base + 0);
            const float s1 = __shfl_sync(full, s, base + 1);
            const float s2 = __shfl_sync(full, s, base + 2);
            const float s3 = __shfl_sync(full, s, base + 3);

            int   k    = 0;
            float best = s0;
            if (s1 > best) { best = s1; k = 1; }
            if (s2 > best) { best = s2; k = 2; }
            if (s3 > best) { best = s3; k = 3; }
            if (p == 0) sidx[w] = 2 * w + (k >> 1) * 64 + (k & 1);
        }
        __syncthreads();

        // ---- Phase 2: gather winner for every t; one window per thread,
        //      8 t-groups, 128B/warp coalesced, streaming stores. ----
        {
            const int g  = tid >> 5;       // 0..7
            const int wl = tid & 31;
            const int idx = sidx[wl];
            float* ob = out + (size_t)bc * (T_ * OHW_) + r * NWIN + wl;
            #pragma unroll
            for (int t = g; t < T_; t += 8) {
                __stcs(&ob[(size_t)t * OHW_], buf[t * 128 + idx]);
            }
        }
        __syncthreads();                   // buffer free for reuse
        cur ^= 1;
    }
}

extern "C" void kernel_launch(void* const* d_in, const int* in_sizes, int n_in,
                              void* d_out, int out_size) {
    const float* x = (const float*)d_in[0];
    float* out = (float*)d_out;

    cudaFuncSetAttribute(spike_pool_persist,
                         cudaFuncAttributeMaxDynamicSharedMemorySize, SMEM_BYTES);

    spike_pool_persist<<<NBLOCKS, NTHREADS, SMEM_BYTES>>>(
        x, out, (long long)out_size);
}